// round 13
// baseline (speedup 1.0000x reference)
#include <cuda_runtime.h>
#include <cuda_fp16.h>
#include <cstdint>

// Problem shape (fixed by dataset)
#define BB 8
#define SS 2048
#define DD 1024
#define OO 1024
#define LCH 32            // scan chunk length
#define NCH (SS / LCH)    // 64 chunks

// ---------------- device scratch (no allocations allowed) ----------------
__device__ float   g_carry[BB * NCH * DD];            // 2 MB
__device__ __half  g_hs[(size_t)BB * SS * DD];        // 32 MB  fp16(h)
__device__ __half  g_bct[(size_t)OO * DD];            // 2 MB   fp16(BC^T)
__device__ int     g_tile_counter;

// ---------------- helpers --------------------------------------------------
__device__ __forceinline__ uint32_t smem_u32(const void* p) {
    uint32_t a;
    asm("{ .reg .u64 t; cvta.to.shared.u64 t, %1; cvt.u32.u64 %0, t; }"
        : "=r"(a) : "l"(p));
    return a;
}

#define SW128(off) ((off) ^ (((off) >> 3) & 0x70))

#define CP_ASYNC_16(dst_smem, src_gmem) \
    asm volatile("cp.async.cg.shared.global [%0], [%1], 16;" \
                 :: "r"(dst_smem), "l"(src_gmem) : "memory")
#define CP_COMMIT() asm volatile("cp.async.commit_group;" ::: "memory")
#define CP_WAIT_GROUP(n) asm volatile("cp.async.wait_group %0;" :: "n"(n) : "memory")

#define LDSM_X4(r0, r1, r2, r3, addr) \
    asm volatile("ldmatrix.sync.aligned.m8n8.x4.shared.b16 {%0,%1,%2,%3}, [%4];" \
                 : "=r"(r0), "=r"(r1), "=r"(r2), "=r"(r3) : "r"(addr))

#define MMA_F16(c, a, b) \
    asm volatile("mma.sync.aligned.m16n8k16.row.col.f32.f16.f16.f32 " \
                 "{%0,%1,%2,%3}, {%4,%5,%6,%7}, {%8,%9}, {%0,%1,%2,%3};" \
                 : "+f"((c)[0]), "+f"((c)[1]), "+f"((c)[2]), "+f"((c)[3]) \
                 : "r"((a)[0]), "r"((a)[1]), "r"((a)[2]), "r"((a)[3]), \
                   "r"((b)[0]), "r"((b)[1]))

#define NPERS 296
#define NTILES 1024          // 128 m-tiles x 8 n-tiles

// ---------------- Kernel 1: prep = carry scan + BC transpose + reset ------
// blocks [0, 1024): per-chunk carries (float2/thread, 262144 lanes)
// blocks [1024, 2048): BC transpose 32x32 tiles
__global__ __launch_bounds__(256)
void prep_kernel(const float* __restrict__ x,
                 const float* __restrict__ A,
                 const float* __restrict__ bc) {
    int tid = threadIdx.x;
    if (blockIdx.x == 0 && tid == 0) g_tile_counter = NPERS;

    if (blockIdx.x < 1024) {
        // ---- per-chunk carries ----
        int idx = blockIdx.x * 256 + tid;          // 0..262143
        int d = (idx & (DD / 2 - 1)) * 2;
        int chunk = (idx >> 9) & (NCH - 1);
        int b = idx >> 15;
        float2 a = *(const float2*)(A + d);
        const float* xp = x + ((size_t)(b * SS + chunk * LCH)) * DD + d;
        float2 h = make_float2(0.0f, 0.0f);
#pragma unroll 8
        for (int i = 0; i < LCH; i++) {
            float2 xv = *(const float2*)(xp + (size_t)i * DD);
            h.x = fmaf(h.x, a.x, xv.x);
            h.y = fmaf(h.y, a.y, xv.y);
        }
        *(float2*)(g_carry + (size_t)((b * NCH + chunk) * DD) + d) = h;
    } else {
        // ---- BC [D,O] -> fp16 BC^T [O,D] ----
        __shared__ float tile[32][33];
        int tb = blockIdx.x - 1024;                // 0..1023
        int o0 = (tb & 31) * 32;
        int d0 = (tb >> 5) * 32;
        int tx = tid & 31, ty = tid >> 5;          // 32 x 8
#pragma unroll
        for (int j = 0; j < 32; j += 8) {
            tile[ty + j][tx] = bc[(size_t)(d0 + ty + j) * OO + o0 + tx];
        }
        __syncthreads();
#pragma unroll
        for (int j = 0; j < 32; j += 8) {
            size_t oi = (size_t)(o0 + ty + j) * DD + d0 + tx;
            g_bct[oi] = __float2half_rn(tile[tx][ty + j]);
        }
    }
}

// ---------------- Kernel 2: carry-corrected emit -> fp16 ------------------
__global__ __launch_bounds__(256)
void scan_emit_kernel(const float* __restrict__ x,
                      const float* __restrict__ A) {
    int idx = blockIdx.x * blockDim.x + threadIdx.x;   // 262144 lanes
    int d = (idx & (DD / 2 - 1)) * 2;
    int chunk = (idx >> 9) & (NCH - 1);
    int b = idx >> 15;
    float2 a = *(const float2*)(A + d);
    float2 aL = a;
#pragma unroll
    for (int s = 0; s < 5; s++) { aL.x *= aL.x; aL.y *= aL.y; }   // a^32
    float2 h = make_float2(0.0f, 0.0f);
    for (int j = 0; j < chunk; j++) {
        float2 cv = *(const float2*)(g_carry + (size_t)((b * NCH + j) * DD) + d);
        h.x = fmaf(h.x, aL.x, cv.x);
        h.y = fmaf(h.y, aL.y, cv.y);
    }
    size_t base = ((size_t)(b * SS + chunk * LCH)) * DD + d;
#pragma unroll 8
    for (int i = 0; i < LCH; i++) {
        size_t off = base + (size_t)i * DD;
        float2 xv = *(const float2*)(x + off);
        h.x = fmaf(h.x, a.x, xv.x);
        h.y = fmaf(h.y, a.y, xv.y);
        *(__half2*)(g_hs + off) = __float22half2_rn(h);
    }
}

// ---------------- Kernel 3: persistent pipelined fp16 HMMA GEMM -----------
// out[r, n] = sum_k h[r, k] * BC[k, n]
#define TM 128
#define TN 128
#define KT 64
#define NKC (DD / KT)        // 16 K-chunks
#define STAGES 3
#define TILE_BYTES (128 * 128)          // one operand tile: 128 rows x 128B
#define STAGE_BYTES (2 * TILE_BYTES)    // A, B  = 32 KB
#define SM_GEMM (STAGES * STAGE_BYTES)  // 96 KB  -> 2 CTAs/SM

// tile id t: m-major within n column:  m0 = (t & 127)*128, n0 = (t >> 7)*128
__device__ __forceinline__ void load_stage(uint32_t stage_base, int t,
                                           int kc, int tid) {
    int m0 = (t & 127) << 7;
    int n0 = (t >> 7) << 7;
    int k0 = kc * KT;
#pragma unroll
    for (int i = 0; i < 8; i++) {
        int c = i * 256 + tid;          // 0..2047
        int tile = c >> 10;             // 0:A 1:B
        int rem = c & 1023;
        int row = rem >> 3;
        int ch = rem & 7;
        uint32_t soff = SW128((uint32_t)(row * 128 + ch * 16));
        uint32_t daddr = stage_base + tile * TILE_BYTES + soff;
        const __half* gp = (tile == 0)
            ? g_hs  + (size_t)(m0 + row) * DD + k0 + ch * 8
            : g_bct + (size_t)(n0 + row) * DD + k0 + ch * 8;
        CP_ASYNC_16(daddr, gp);
    }
}

__global__ __launch_bounds__(256, 2)
void gemm_f16_kernel(float* __restrict__ out) {
    extern __shared__ __align__(1024) char smem[];
    uint32_t sb = smem_u32(smem);
    __shared__ int s_next;
    int tid = threadIdx.x;
    int wid = tid >> 5;
    int lane = tid & 31;
    int wm = wid & 3;           // 4 warps along M
    int wn = wid >> 2;          // 2 warps along N

    int a_row = wm * 32 + (lane & 15);
    int a_chb = ((lane >> 4) & 1) * 16;
    int b_row = wn * 64 + ((lane >> 4) & 1) * 8 + (lane & 7);
    int b_chb = ((lane >> 3) & 1) * 16;

    int tile = blockIdx.x;      // first tile: static (grid = NPERS < NTILES)
    int lstage = 2;             // next stage slot to fill
    int cstage = 0;             // stage slot to consume

    // prologue: chunks 0,1 of first tile
    load_stage(sb + 0 * STAGE_BYTES, tile, 0, tid); CP_COMMIT();
    load_stage(sb + 1 * STAGE_BYTES, tile, 1, tid); CP_COMMIT();

    while (true) {
        int m0 = (tile & 127) << 7;
        int n0 = (tile >> 7) << 7;

        float acc[2][8][4];
#pragma unroll
        for (int mi = 0; mi < 2; mi++)
#pragma unroll
            for (int ni = 0; ni < 8; ni++)
#pragma unroll
                for (int c = 0; c < 4; c++) acc[mi][ni][c] = 0.0f;

        for (int kc = 0; kc < NKC; kc++) {
            CP_WAIT_GROUP(1);
            __syncthreads();

            // fetch next tile id early (visible by kc==14 via later syncs)
            if (kc == 11 && tid == 0) s_next = atomicAdd(&g_tile_counter, 1);

            if (kc + 2 < NKC) {
                load_stage(sb + lstage * STAGE_BYTES, tile, kc + 2, tid);
            } else {
                int tn = s_next;
                if (tn < NTILES)
                    load_stage(sb + lstage * STAGE_BYTES, tn, kc + 2 - NKC, tid);
            }
            CP_COMMIT();
            lstage = (lstage == 2) ? 0 : lstage + 1;

            uint32_t st = sb + cstage * STAGE_BYTES;
            cstage = (cstage == 2) ? 0 : cstage + 1;
            uint32_t s_a = st;
            uint32_t s_b = st + TILE_BYTES;

#pragma unroll
            for (int ks = 0; ks < KT / 16; ks++) {
                uint32_t af[2][4];
                uint32_t bf[8][2];
#pragma unroll
                for (int mi = 0; mi < 2; mi++) {
                    uint32_t off = SW128((uint32_t)((a_row + mi * 16) * 128 + ks * 32 + a_chb));
                    LDSM_X4(af[mi][0], af[mi][1], af[mi][2], af[mi][3], s_a + off);
                }
#pragma unroll
                for (int p = 0; p < 4; p++) {
                    uint32_t off = SW128((uint32_t)((b_row + p * 16) * 128 + ks * 32 + b_chb));
                    uint32_t t0, t1, t2, t3;
                    LDSM_X4(t0, t1, t2, t3, s_b + off);
                    bf[2 * p][0] = t0; bf[2 * p][1] = t1;
                    bf[2 * p + 1][0] = t2; bf[2 * p + 1][1] = t3;
                }
#pragma unroll
                for (int mi = 0; mi < 2; mi++)
#pragma unroll
                    for (int ni = 0; ni < 8; ni++)
                        MMA_F16(acc[mi][ni], af[mi], bf[ni]);
            }
        }

        // epilogue for this tile (no smem use -> no extra sync needed)
#pragma unroll
        for (int mi = 0; mi < 2; mi++) {
#pragma unroll
            for (int ni = 0; ni < 8; ni++) {
                int row = m0 + wm * 32 + mi * 16 + (lane >> 2);
                int col = n0 + wn * 64 + ni * 8 + 2 * (lane & 3);
                float2 v0 = make_float2(acc[mi][ni][0], acc[mi][ni][1]);
                float2 v1 = make_float2(acc[mi][ni][2], acc[mi][ni][3]);
                *(float2*)(out + (size_t)row * OO + col) = v0;
                *(float2*)(out + (size_t)(row + 8) * OO + col) = v1;
            }
        }

        tile = s_next;          // written at kc==11, stable since
        if (tile >= NTILES) break;
    }
}

// ---------------- launch --------------------------------------------------
extern "C" void kernel_launch(void* const* d_in, const int* in_sizes, int n_in,
                              void* d_out, int out_size) {
    const float* x  = (const float*)d_in[0];   // [B, S, D]
    const float* A  = (const float*)d_in[1];   // [D]
    const float* BC = (const float*)d_in[2];   // [D, O]
    float* out = (float*)d_out;                // [B, S, O]
    (void)in_sizes; (void)n_in; (void)out_size;

    prep_kernel<<<2048, 256>>>(x, A, BC);          // carry + BC^T + reset
    scan_emit_kernel<<<1024, 256>>>(x, A);

    cudaFuncSetAttribute(gemm_f16_kernel,
                         cudaFuncAttributeMaxDynamicSharedMemorySize, SM_GEMM);
    gemm_f16_kernel<<<NPERS, 256, SM_GEMM>>>(out);
}

// round 14
// speedup vs baseline: 1.0030x; 1.0030x over previous
#include <cuda_runtime.h>
#include <cuda_fp16.h>
#include <cstdint>

// Problem shape (fixed by dataset)
#define BB 8
#define SS 2048
#define DD 1024
#define OO 1024
#define LCH 64            // scan chunk length
#define NCH (SS / LCH)    // 32 chunks

// ---------------- device scratch (no allocations allowed) ----------------
__device__ float   g_carry[BB * NCH * DD];            // 1 MB
__device__ __half  g_hs[(size_t)BB * SS * DD];        // 32 MB  fp16(h)
__device__ __half  g_bct[(size_t)OO * DD];            // 2 MB   fp16(BC^T)
__device__ int     g_tile_counter;

// ---------------- helpers --------------------------------------------------
__device__ __forceinline__ uint32_t smem_u32(const void* p) {
    uint32_t a;
    asm("{ .reg .u64 t; cvta.to.shared.u64 t, %1; cvt.u32.u64 %0, t; }"
        : "=r"(a) : "l"(p));
    return a;
}

#define SW128(off) ((off) ^ (((off) >> 3) & 0x70))

#define CP_ASYNC_16(dst_smem, src_gmem) \
    asm volatile("cp.async.cg.shared.global [%0], [%1], 16;" \
                 :: "r"(dst_smem), "l"(src_gmem) : "memory")
#define CP_COMMIT() asm volatile("cp.async.commit_group;" ::: "memory")
#define CP_WAIT_GROUP(n) asm volatile("cp.async.wait_group %0;" :: "n"(n) : "memory")

#define LDSM_X4(r0, r1, r2, r3, addr) \
    asm volatile("ldmatrix.sync.aligned.m8n8.x4.shared.b16 {%0,%1,%2,%3}, [%4];" \
                 : "=r"(r0), "=r"(r1), "=r"(r2), "=r"(r3) : "r"(addr))

#define MMA_F16(c, a, b) \
    asm volatile("mma.sync.aligned.m16n8k16.row.col.f32.f16.f16.f32 " \
                 "{%0,%1,%2,%3}, {%4,%5,%6,%7}, {%8,%9}, {%0,%1,%2,%3};" \
                 : "+f"((c)[0]), "+f"((c)[1]), "+f"((c)[2]), "+f"((c)[3]) \
                 : "r"((a)[0]), "r"((a)[1]), "r"((a)[2]), "r"((a)[3]), \
                   "r"((b)[0]), "r"((b)[1]))

#define NPERS 296
#define NTILES 1024          // 128 m-tiles x 8 n-tiles

// tile id t -> (m0, n0): paired n-columns so consecutive tiles share A rows
__device__ __forceinline__ int tile_m0(int t) { return ((t >> 1) & 127) << 7; }
__device__ __forceinline__ int tile_n0(int t) {
    return ((((t >> 8) << 1) | (t & 1))) << 7;
}

// ---------------- Kernel 1: prep = carry scan + BC transpose + reset ------
// blocks [0, 512): per-chunk carries (float2/thread, 131072 lanes)
// blocks [512, 1536): BC transpose 32x32 tiles
__global__ __launch_bounds__(256)
void prep_kernel(const float* __restrict__ x,
                 const float* __restrict__ A,
                 const float* __restrict__ bc) {
    int tid = threadIdx.x;
    if (blockIdx.x == 0 && tid == 0) g_tile_counter = NPERS;

    if (blockIdx.x < 512) {
        // ---- per-chunk carries ----
        int idx = blockIdx.x * 256 + tid;          // 0..131071
        int d = (idx & (DD / 2 - 1)) * 2;
        int chunk = (idx >> 9) & (NCH - 1);
        int b = idx >> 14;
        float2 a = *(const float2*)(A + d);
        const float* xp = x + ((size_t)(b * SS + chunk * LCH)) * DD + d;
        float2 h = make_float2(0.0f, 0.0f);
#pragma unroll 8
        for (int i = 0; i < LCH; i++) {
            float2 xv = *(const float2*)(xp + (size_t)i * DD);
            h.x = fmaf(h.x, a.x, xv.x);
            h.y = fmaf(h.y, a.y, xv.y);
        }
        *(float2*)(g_carry + (size_t)((b * NCH + chunk) * DD) + d) = h;
    } else {
        // ---- BC [D,O] -> fp16 BC^T [O,D] ----
        __shared__ float tile[32][33];
        int tb = blockIdx.x - 512;                 // 0..1023
        int o0 = (tb & 31) * 32;
        int d0 = (tb >> 5) * 32;
        int tx = tid & 31, ty = tid >> 5;          // 32 x 8
#pragma unroll
        for (int j = 0; j < 32; j += 8) {
            tile[ty + j][tx] = bc[(size_t)(d0 + ty + j) * OO + o0 + tx];
        }
        __syncthreads();
#pragma unroll
        for (int j = 0; j < 32; j += 8) {
            size_t oi = (size_t)(o0 + ty + j) * DD + d0 + tx;
            g_bct[oi] = __float2half_rn(tile[tx][ty + j]);
        }
    }
}

// ---------------- Kernel 2: carry-corrected emit -> fp16 ------------------
__global__ __launch_bounds__(256)
void scan_emit_kernel(const float* __restrict__ x,
                      const float* __restrict__ A) {
    int idx = blockIdx.x * blockDim.x + threadIdx.x;   // 131072 lanes
    int d = (idx & (DD / 2 - 1)) * 2;
    int chunk = (idx >> 9) & (NCH - 1);
    int b = idx >> 14;
    float2 a = *(const float2*)(A + d);
    float2 aL = a;
#pragma unroll
    for (int s = 0; s < 6; s++) { aL.x *= aL.x; aL.y *= aL.y; }   // a^64
    float2 h = make_float2(0.0f, 0.0f);
    for (int j = 0; j < chunk; j++) {
        float2 cv = *(const float2*)(g_carry + (size_t)((b * NCH + j) * DD) + d);
        h.x = fmaf(h.x, aL.x, cv.x);
        h.y = fmaf(h.y, aL.y, cv.y);
    }
    size_t base = ((size_t)(b * SS + chunk * LCH)) * DD + d;
#pragma unroll 8
    for (int i = 0; i < LCH; i++) {
        size_t off = base + (size_t)i * DD;
        float2 xv = *(const float2*)(x + off);
        h.x = fmaf(h.x, a.x, xv.x);
        h.y = fmaf(h.y, a.y, xv.y);
        *(__half2*)(g_hs + off) = __float22half2_rn(h);
    }
}

// ---------------- Kernel 3: persistent pipelined fp16 HMMA GEMM -----------
// out[r, n] = sum_k h[r, k] * BC[k, n]
#define TM 128
#define TN 128
#define KT 64
#define NKC (DD / KT)        // 16 K-chunks
#define STAGES 3
#define TILE_BYTES (128 * 128)          // one operand tile: 128 rows x 128B
#define STAGE_BYTES (2 * TILE_BYTES)    // A, B  = 32 KB
#define SM_GEMM (STAGES * STAGE_BYTES)  // 96 KB  -> 2 CTAs/SM

__device__ __forceinline__ void load_stage(uint32_t stage_base, int t,
                                           int kc, int tid) {
    int m0 = tile_m0(t);
    int n0 = tile_n0(t);
    int k0 = kc * KT;
#pragma unroll
    for (int i = 0; i < 8; i++) {
        int c = i * 256 + tid;          // 0..2047
        int tile = c >> 10;             // 0:A 1:B
        int rem = c & 1023;
        int row = rem >> 3;
        int ch = rem & 7;
        uint32_t soff = SW128((uint32_t)(row * 128 + ch * 16));
        uint32_t daddr = stage_base + tile * TILE_BYTES + soff;
        const __half* gp = (tile == 0)
            ? g_hs  + (size_t)(m0 + row) * DD + k0 + ch * 8
            : g_bct + (size_t)(n0 + row) * DD + k0 + ch * 8;
        CP_ASYNC_16(daddr, gp);
    }
}

__global__ __launch_bounds__(256, 2)
void gemm_f16_kernel(float* __restrict__ out) {
    extern __shared__ __align__(1024) char smem[];
    uint32_t sb = smem_u32(smem);
    __shared__ int s_next;
    int tid = threadIdx.x;
    int wid = tid >> 5;
    int lane = tid & 31;
    int wm = wid & 3;           // 4 warps along M
    int wn = wid >> 2;          // 2 warps along N

    int a_row = wm * 32 + (lane & 15);
    int a_chb = ((lane >> 4) & 1) * 16;
    int b_row = wn * 64 + ((lane >> 4) & 1) * 8 + (lane & 7);
    int b_chb = ((lane >> 3) & 1) * 16;

    int tile = blockIdx.x;      // first tile: static (grid = NPERS < NTILES)
    int lstage = 2;             // next stage slot to fill
    int cstage = 0;             // stage slot to consume

    // prologue: chunks 0,1 of first tile
    load_stage(sb + 0 * STAGE_BYTES, tile, 0, tid); CP_COMMIT();
    load_stage(sb + 1 * STAGE_BYTES, tile, 1, tid); CP_COMMIT();

    while (true) {
        int m0 = tile_m0(tile);
        int n0 = tile_n0(tile);

        float acc[2][8][4];
#pragma unroll
        for (int mi = 0; mi < 2; mi++)
#pragma unroll
            for (int ni = 0; ni < 8; ni++)
#pragma unroll
                for (int c = 0; c < 4; c++) acc[mi][ni][c] = 0.0f;

        for (int kc = 0; kc < NKC; kc++) {
            CP_WAIT_GROUP(1);
            __syncthreads();

            // fetch next tile id early (visible by kc==14 via later syncs)
            if (kc == 11 && tid == 0) s_next = atomicAdd(&g_tile_counter, 1);

            if (kc + 2 < NKC) {
                load_stage(sb + lstage * STAGE_BYTES, tile, kc + 2, tid);
            } else {
                int tn = s_next;
                if (tn < NTILES)
                    load_stage(sb + lstage * STAGE_BYTES, tn, kc + 2 - NKC, tid);
            }
            CP_COMMIT();
            lstage = (lstage == 2) ? 0 : lstage + 1;

            uint32_t st = sb + cstage * STAGE_BYTES;
            cstage = (cstage == 2) ? 0 : cstage + 1;
            uint32_t s_a = st;
            uint32_t s_b = st + TILE_BYTES;

#pragma unroll
            for (int ks = 0; ks < KT / 16; ks++) {
                uint32_t af[2][4];
                uint32_t bf[8][2];
#pragma unroll
                for (int mi = 0; mi < 2; mi++) {
                    uint32_t off = SW128((uint32_t)((a_row + mi * 16) * 128 + ks * 32 + a_chb));
                    LDSM_X4(af[mi][0], af[mi][1], af[mi][2], af[mi][3], s_a + off);
                }
#pragma unroll
                for (int p = 0; p < 4; p++) {
                    uint32_t off = SW128((uint32_t)((b_row + p * 16) * 128 + ks * 32 + b_chb));
                    uint32_t t0, t1, t2, t3;
                    LDSM_X4(t0, t1, t2, t3, s_b + off);
                    bf[2 * p][0] = t0; bf[2 * p][1] = t1;
                    bf[2 * p + 1][0] = t2; bf[2 * p + 1][1] = t3;
                }
#pragma unroll
                for (int mi = 0; mi < 2; mi++)
#pragma unroll
                    for (int ni = 0; ni < 8; ni++)
                        MMA_F16(acc[mi][ni], af[mi], bf[ni]);
            }
        }

        // epilogue for this tile (no smem use -> no extra sync needed)
#pragma unroll
        for (int mi = 0; mi < 2; mi++) {
#pragma unroll
            for (int ni = 0; ni < 8; ni++) {
                int row = m0 + wm * 32 + mi * 16 + (lane >> 2);
                int col = n0 + wn * 64 + ni * 8 + 2 * (lane & 3);
                float2 v0 = make_float2(acc[mi][ni][0], acc[mi][ni][1]);
                float2 v1 = make_float2(acc[mi][ni][2], acc[mi][ni][3]);
                *(float2*)(out + (size_t)row * OO + col) = v0;
                *(float2*)(out + (size_t)(row + 8) * OO + col) = v1;
            }
        }

        tile = s_next;          // written at kc==11, stable since
        if (tile >= NTILES) break;
    }
}

// ---------------- launch --------------------------------------------------
extern "C" void kernel_launch(void* const* d_in, const int* in_sizes, int n_in,
                              void* d_out, int out_size) {
    const float* x  = (const float*)d_in[0];   // [B, S, D]
    const float* A  = (const float*)d_in[1];   // [D]
    const float* BC = (const float*)d_in[2];   // [D, O]
    float* out = (float*)d_out;                // [B, S, O]
    (void)in_sizes; (void)n_in; (void)out_size;

    prep_kernel<<<1536, 256>>>(x, A, BC);          // carry + BC^T + reset
    scan_emit_kernel<<<512, 256>>>(x, A);

    cudaFuncSetAttribute(gemm_f16_kernel,
                         cudaFuncAttributeMaxDynamicSharedMemorySize, SM_GEMM);
    gemm_f16_kernel<<<NPERS, 256, SM_GEMM>>>(out);
}